// round 15
// baseline (speedup 1.0000x reference)
#include <cuda_runtime.h>
#include <cuda_bf16.h>
#include <cstdint>
#include <math.h>

#define L_ 256
#define D_ 300
#define S_ 16
#define K_ 16
#define E_ 2048
#define C_ 7
#define NEG_ (-1000000000.0f)
#define D4_ 75
#define GST 3            // cp.async pipeline stages

// ---------------- scratch ---------------------------------------------------
__device__ float g_Y0[L_ * D_];
__device__ float g_Y1[L_ * D_];
__device__ float g_Q[L_ * D_];
__device__ float g_Km[L_ * D_];
__device__ float g_Vm[L_ * D_];
__device__ float g_xws[L_ * D_];
__device__ float g_rel[L_ * D_];
__device__ float g_feat[L_ * 3 * D_];
__device__ float g_nodes[L_ * 3 * S_ * D_];
__device__ float g_scoreb[L_ * 3 * S_];
__device__ int   g_nmask[L_ * 3 * S_];
__device__ float g_h1[L_ * D_];

__device__ __forceinline__ float wred(float v) {
#pragma unroll
    for (int o = 16; o; o >>= 1) v += __shfl_xor_sync(0xFFFFFFFFu, v, o);
    return v;
}
__device__ __forceinline__ float dot4(float4 a, float4 b) {
    return a.x * b.x + a.y * b.y + a.z * b.z + a.w * b.w;
}
// forced (non-CSE-able) vector load for the re-load pass
__device__ __forceinline__ float4 ldg4v(const float4* p) {
    float4 v;
    asm volatile("ld.global.v4.f32 {%0,%1,%2,%3}, [%4];"
                 : "=f"(v.x), "=f"(v.y), "=f"(v.z), "=f"(v.w) : "l"(p));
    return v;
}

// ---------------- cp.async helpers ------------------------------------------
__device__ __forceinline__ void cpa16(unsigned int dst, const float* src, bool p) {
    asm volatile("cp.async.cg.shared.global [%0], [%1], 16, %2;"
                 :: "r"(dst), "l"(src), "r"(p ? 16 : 0));
}
__device__ __forceinline__ void cpcommit() {
    asm volatile("cp.async.commit_group;");
}
template<int N>
__device__ __forceinline__ void cpwait() {
    asm volatile("cp.async.wait_group %0;" :: "n"(N));
}

// ---------------- 3-stage cp.async pipelined 32x32 GEMM ---------------------
__device__ __forceinline__ void gemm_core_async(
    const float* __restrict__ A, const float* __restrict__ B,
    const float* __restrict__ bias, float* __restrict__ C,
    int M, int N, int K, int ldc, int relu,
    float (*As)[32][36], float (*Bs)[32][36])
{
    int t  = threadIdx.x;
    int lr = t >> 3;
    int lc = (t & 7) << 2;
    int tx = t & 31, ty = t >> 5;
    int row0 = blockIdx.y * 32;
    int col0 = blockIdx.x * 32;
    int T = (K + 31) >> 5;

    unsigned int sA = (unsigned int)__cvta_generic_to_shared(&As[0][0][0]);
    unsigned int sB = (unsigned int)__cvta_generic_to_shared(&Bs[0][0][0]);
    const unsigned int stageB = 32 * 36 * 4;
    unsigned int off = (unsigned int)(lr * 36 + lc) * 4;

    float acc[4] = {0.f, 0.f, 0.f, 0.f};

#pragma unroll
    for (int s = 0; s < GST - 1; s++) {
        if (s < T) {
            int k0 = s << 5;
            bool pa = (row0 + lr < M) && (k0 + lc < K);
            const float* pas = pa ? A + (size_t)(row0 + lr) * K + k0 + lc : A;
            cpa16(sA + s * stageB + off, pas, pa);
            bool pb = (k0 + lr < K) && (col0 + lc < N);
            const float* pbs = pb ? B + (size_t)(k0 + lr) * N + col0 + lc : B;
            cpa16(sB + s * stageB + off, pbs, pb);
        }
        cpcommit();
    }

    for (int t0 = 0; t0 < T; t0++) {
        int tl = t0 + GST - 1;
        if (tl < T) {
            int st = tl % GST;
            int k0 = tl << 5;
            bool pa = (row0 + lr < M) && (k0 + lc < K);
            const float* pas = pa ? A + (size_t)(row0 + lr) * K + k0 + lc : A;
            cpa16(sA + st * stageB + off, pas, pa);
            bool pb = (k0 + lr < K) && (col0 + lc < N);
            const float* pbs = pb ? B + (size_t)(k0 + lr) * N + col0 + lc : B;
            cpa16(sB + st * stageB + off, pbs, pb);
        }
        cpcommit();
        cpwait<GST - 2>();
        __syncthreads();
        int st = t0 % GST;
#pragma unroll
        for (int kk = 0; kk < 32; kk++) {
            float bv = Bs[st][kk][tx];
#pragma unroll
            for (int i = 0; i < 4; i++) acc[i] += As[st][ty + 8 * i][kk] * bv;
        }
        __syncthreads();
    }

    int col = col0 + tx;
    if (col < N) {
        float bv = bias ? bias[col] : 0.f;
#pragma unroll
        for (int i = 0; i < 4; i++) {
            int r = row0 + ty + 8 * i;
            if (r < M) {
                float v = acc[i] + bv;
                if (relu) v = fmaxf(v, 0.f);
                C[(size_t)r * ldc + col] = v;
            }
        }
    }
}

struct Batch6 {
    const float* B[6];
    const float* bias[6];
    float* C[6];
};

__global__ void gemm6_kernel(const float* __restrict__ A, Batch6 p)
{
    __shared__ float As[GST][32][36];
    __shared__ float Bs[GST][32][36];
    int z = blockIdx.z;
    gemm_core_async(A, p.B[z], p.bias[z], p.C[z], L_, D_, D_, D_, 0, As, Bs);
}

__global__ void gemm_kernel(const float* __restrict__ A, const float* __restrict__ B,
                            const float* __restrict__ bias, float* __restrict__ C,
                            int M, int N, int K, int ldc, int relu)
{
    __shared__ float As[GST][32][36];
    __shared__ float Bs[GST][32][36];
    gemm_core_async(A, B, bias, C, M, N, K, ldc, relu, As, Bs);
}

// ---------------- RGCN + (windowed attention fused with Wo GEMV) ------------
__global__ void combo_kernel(const int* __restrict__ esrc, const int* __restrict__ edst,
                             const int* __restrict__ etyp, const float* __restrict__ comp,
                             const float* __restrict__ Wo)
{
    int tid = threadIdx.x;          // 640 threads
    if (blockIdx.x < L_) {
        int l = blockIdx.x;
        __shared__ int s_src[E_ / 2], s_dst[E_ / 2], s_typ[E_ / 2];
        __shared__ float scomp[12];
        __shared__ float part[D_];
        if (tid < 12) scomp[tid] = comp[tid];
        int half = tid >= 320;
        int jt = half ? tid - 320 : tid;
        float acc = 0.f;
        for (int pass = 0; pass < 2; pass++) {
            for (int e = tid; e < E_ / 2; e += 640) {
                int ge = pass * (E_ / 2) + e;
                s_src[e] = esrc[ge];
                s_dst[e] = edst[ge];
                s_typ[e] = etyp[ge];
            }
            __syncthreads();
            if (jt < D_) {
                int e0 = half ? E_ / 4 : 0;
                int e1 = half ? E_ / 2 : E_ / 4;
                for (int e = e0; e < e1; e++) {
                    if (s_dst[e] == l) {
                        int s = s_src[e], ty = s_typ[e];
                        acc += scomp[ty * 2] * g_Y0[s * D_ + jt]
                             + scomp[ty * 2 + 1] * g_Y1[s * D_ + jt];
                    }
                }
            }
            __syncthreads();
        }
        if (!half && jt < D_) part[jt] = acc;
        __syncthreads();
        if (half && jt < D_) part[jt] += acc;
        __syncthreads();
        if (!half && jt < D_)
            g_feat[l * 3 * D_ + jt] = g_xws[l * D_ + jt] + part[jt];
    } else {
        int l = blockIdx.x - L_;
        int wid = tid >> 5, lane = tid & 31;
        __shared__ float sS[2][3];
        __shared__ float sA[2][3];
        __shared__ float sat[D_];
        int nbr[3];
        nbr[0] = l > 0 ? l - 1 : 0;
        nbr[1] = l;
        nbr[2] = l < L_ - 1 ? l + 1 : L_ - 1;
        if (wid < 6) {
            int h = wid / 3, k = wid % 3;
            const float* q  = g_Q  + l * D_ + h * 150;
            const float* kk = g_Km + nbr[k] * D_ + h * 150;
            float a = 0.f;
            for (int j = lane; j < 150; j += 32) a += q[j] * kk[j];
            a = wred(a);
            if (lane == 0) sS[h][k] = a * rsqrtf(150.f);
        }
        __syncthreads();
        if (tid < 2) {
            float m = fmaxf(sS[tid][0], fmaxf(sS[tid][1], sS[tid][2]));
            float e0 = expf(sS[tid][0] - m), e1 = expf(sS[tid][1] - m), e2 = expf(sS[tid][2] - m);
            float s = e0 + e1 + e2;
            sA[tid][0] = e0 / s; sA[tid][1] = e1 / s; sA[tid][2] = e2 / s;
        }
        __syncthreads();
        for (int j = tid; j < D_; j += 640) {
            int hh = j / 150;
            float acc = 0.f;
#pragma unroll
            for (int kx = 0; kx < 3; kx++) acc += sA[hh][kx] * g_Vm[nbr[kx] * D_ + j];
            sat[j] = acc;
        }
        __syncthreads();
        for (int c = tid; c < D_; c += 640) {
            float a = 0.f;
#pragma unroll 8
            for (int j = 0; j < D_; j++) a += sat[j] * Wo[j * D_ + c];
            g_rel[l * D_ + c] = a;
            g_feat[l * 3 * D_ + D_ + c] = a;
        }
    }
}

// ---------------- concept attention: low-smem variant -----------------------
// rows gathered to regs for dots; re-loaded (forced LDG, L1-hot) for the
// weighted sum into per-warp partial slabs. smem ~13.6KB -> ~2x residency.
__global__ void concept_kernel(const int* __restrict__ src_ids, const int* __restrict__ dst_ids,
                               const float* __restrict__ wgt, const float* __restrict__ sen,
                               const float* __restrict__ table, const float* __restrict__ rvecs)
{
    int u = blockIdx.x;
    int s = u % S_;
    int l = (u / S_) % L_;
    int g = u / (S_ * L_);
    int tid = threadIdx.x;              // 256 threads, 8 warps
    int lane = tid & 31, wid = tid >> 5;

    __shared__ float4 part4[8][D4_];
    __shared__ float4 su4[D4_];
    __shared__ float4 ssrc4[D4_];
    __shared__ float4 rv4s[D4_];
    __shared__ float du[K_], dsr[K_], dn[K_], beta[K_];
    __shared__ int   dmask[K_];
    __shared__ float red[8];
    __shared__ float s_unorm;

    int base = u * K_;
    int r0 = wid * 2, r1 = r0 + 1;
    int pr = (lane < 2) ? dst_ids[base + r0 + lane] : 0;
    int id0 = __shfl_sync(0xFFFFFFFFu, pr, 0);
    int id1 = __shfl_sync(0xFFFFFFFFu, pr, 1);
    if (lane < 2) dmask[r0 + lane] = (pr >= 0);
    int sid = src_ids[u];
    int smask = (sid >= 0);
    if (sid < 0) sid = 0;

    const float4* d0 = (const float4*)(table + (size_t)(id0 >= 0 ? id0 : 0) * D_);
    const float4* d1 = (const float4*)(table + (size_t)(id1 >= 0 ? id1 : 0) * D_);
    bool g3 = (lane + 64) < D4_;
    float4 z4 = make_float4(0.f, 0.f, 0.f, 0.f);

    // shared vectors
    const float4* rv4p = (const float4*)(rvecs + g * D_);
    if (tid < D4_) {
        float4 sv = ((const float4*)(table + (size_t)sid * D_))[tid];
        ssrc4[tid] = sv;
        rv4s[tid]  = rv4p[tid];
        su4[tid]   = ((const float4*)(g_rel + l * D_))[tid];
    }
    __syncthreads();

    // gather rows to registers + dots (rows die after this scope)
    {
        float4 v0a = d0[lane],      v1a = d1[lane];
        float4 v0b = d0[lane + 32], v1b = d1[lane + 32];
        float4 v0c = g3 ? d0[lane + 64] : z4;
        float4 v1c = g3 ? d1[lane + 64] : z4;
        float4 ua = su4[lane], ub = su4[lane + 32], uc = g3 ? su4[lane + 64] : z4;
        float4 sa = ssrc4[lane], sb = ssrc4[lane + 32], sc4 = g3 ? ssrc4[lane + 64] : z4;
        float4 ra = rv4s[lane], rb = rv4s[lane + 32], rc = g3 ? rv4s[lane + 64] : z4;
        float4 pa = make_float4(sa.x * ra.x, sa.y * ra.y, sa.z * ra.z, sa.w * ra.w);
        float4 pb = make_float4(sb.x * rb.x, sb.y * rb.y, sb.z * rb.z, sb.w * rb.w);
        float4 pc = make_float4(sc4.x * rc.x, sc4.y * rc.y, sc4.z * rc.z, sc4.w * rc.w);
        float a0 = dot4(ua, v0a) + dot4(ub, v0b) + dot4(uc, v0c);
        float b0 = dot4(pa, v0a) + dot4(pb, v0b) + dot4(pc, v0c);
        float c0 = dot4(v0a, v0a) + dot4(v0b, v0b) + dot4(v0c, v0c);
        float a1 = dot4(ua, v1a) + dot4(ub, v1b) + dot4(uc, v1c);
        float b1 = dot4(pa, v1a) + dot4(pb, v1b) + dot4(pc, v1c);
        float c1 = dot4(v1a, v1a) + dot4(v1b, v1b) + dot4(v1c, v1c);
        a0 = wred(a0); b0 = wred(b0); c0 = wred(c0);
        a1 = wred(a1); b1 = wred(b1); c1 = wred(c1);
        if (lane == 0) {
            du[r0] = a0; dsr[r0] = b0; dn[r0] = c0;
            du[r1] = a1; dsr[r1] = b1; dn[r1] = c1;
        }
        if (wid == 0) {
            float p = dot4(ua, ua) + dot4(ub, ub) + dot4(uc, uc);
            p = wred(p);
            if (lane == 0) s_unorm = sqrtf(p);
        }
    }
    __syncthreads();

    // 16-lane softmax chain -> beta = alpha1 * alpha2
    if (wid == 0) {
        int k = lane & 15;
        int mk = dmask[k];
        float wk = wgt[base + k];
        float se = fabsf(sen[base + k]);
        float unorm = s_unorm;
        float cosv = fabsf(du[k]) / (unorm * sqrtf(dn[k]) + 1e-8f);
        float om = 0.5f * wk * cosv + 0.5f * se;
        float v = mk ? om : NEG_;
        float m = v;
#pragma unroll
        for (int o = 8; o; o >>= 1) m = fmaxf(m, __shfl_xor_sync(0xFFFFFFFFu, m, o));
        float e = expf(v - m);
        float sm = e;
#pragma unroll
        for (int o = 8; o; o >>= 1) sm += __shfl_xor_sync(0xFFFFFFFFu, sm, o);
        float a1v = mk ? e / sm : 0.f;

        float sv = a1v * dsr[k];
        v = mk ? sv : NEG_;
        m = v;
#pragma unroll
        for (int o = 8; o; o >>= 1) m = fmaxf(m, __shfl_xor_sync(0xFFFFFFFFu, m, o));
        e = expf(v - m);
        sm = e;
#pragma unroll
        for (int o = 8; o; o >>= 1) sm += __shfl_xor_sync(0xFFFFFFFFu, sm, o);
        float b2 = a1v * (mk ? e / sm : 0.f);
        if (lane < 16) beta[k] = b2;
    }
    __syncthreads();

    // re-load rows (forced LDG, should be L1-hot) and build per-warp partial
    {
        float b0 = beta[r0], b1 = beta[r1];
        float4 w0 = ldg4v(d0 + lane);
        float4 w1 = ldg4v(d1 + lane);
        part4[wid][lane] = make_float4(b0 * w0.x + b1 * w1.x, b0 * w0.y + b1 * w1.y,
                                       b0 * w0.z + b1 * w1.z, b0 * w0.w + b1 * w1.w);
        w0 = ldg4v(d0 + lane + 32);
        w1 = ldg4v(d1 + lane + 32);
        part4[wid][lane + 32] = make_float4(b0 * w0.x + b1 * w1.x, b0 * w0.y + b1 * w1.y,
                                            b0 * w0.z + b1 * w1.z, b0 * w0.w + b1 * w1.w);
        if (g3) {
            w0 = ldg4v(d0 + lane + 64);
            w1 = ldg4v(d1 + lane + 64);
            part4[wid][lane + 64] = make_float4(b0 * w0.x + b1 * w1.x, b0 * w0.y + b1 * w1.y,
                                                b0 * w0.z + b1 * w1.z, b0 * w0.w + b1 * w1.w);
        }
    }
    __syncthreads();

    // reduce partials -> node row + score
    int node = l * (3 * S_) + g * S_ + s;
    float sc = 0.f;
    if (tid < D4_) {
        float4 a = part4[0][tid];
#pragma unroll
        for (int w = 1; w < 8; w++) {
            float4 p = part4[w][tid];
            a.x += p.x; a.y += p.y; a.z += p.z; a.w += p.w;
        }
        float4 rv = rv4s[tid], sv = ssrc4[tid];
        float4 v = make_float4(fmaf(rv.x, a.x, sv.x), fmaf(rv.y, a.y, sv.y),
                               fmaf(rv.z, a.z, sv.z), fmaf(rv.w, a.w, sv.w));
        ((float4*)(g_nodes + (size_t)node * D_))[tid] = v;
        sc = dot4(v, su4[tid]);
    }
    sc = wred(sc);
    if (lane == 0) red[wid] = sc;
    __syncthreads();
    if (tid == 0) {
        float t = red[0] + red[1] + red[2];  // tid<75 spans warps 0-2
        g_scoreb[node] = t;
        g_nmask[node]  = smask;
    }
}

// ---------------- node attention -> sym -> feat[:,600:900] ------------------
__global__ void sym_kernel()
{
    int l = blockIdx.x;
    int tid = threadIdx.x;        // 256
    int lane = tid & 31, wid = tid >> 5;
    __shared__ float att[3 * S_];
    __shared__ float4 part4[8][D4_];
    if (tid < 3 * S_)
        att[tid] = g_nmask[l * 3 * S_ + tid] ? g_scoreb[l * 3 * S_ + tid] : NEG_;
    __syncthreads();
    if (tid == 0) {
        float mx = -1e30f;
        for (int n = 0; n < 3 * S_; n++) mx = fmaxf(mx, att[n]);
        float sum = 0.f;
        for (int n = 0; n < 3 * S_; n++) { float e = expf(att[n] - mx); att[n] = e; sum += e; }
        for (int n = 0; n < 3 * S_; n++)
            att[n] = g_nmask[l * 3 * S_ + n] ? att[n] / sum : 0.f;
    }
    __syncthreads();
    int n0 = wid * 6;
    for (int j = lane; j < D4_; j += 32) {
        float4 a = make_float4(0.f, 0.f, 0.f, 0.f);
#pragma unroll
        for (int q = 0; q < 6; q++) {
            int n = n0 + q;
            float w = att[n];
            float4 v = ((const float4*)(g_nodes + (size_t)(l * 3 * S_ + n) * D_))[j];
            a.x += w * v.x; a.y += w * v.y; a.z += w * v.z; a.w += w * v.w;
        }
        part4[wid][j] = a;
    }
    __syncthreads();
    if (tid < D4_) {
        float4 a = part4[0][tid];
#pragma unroll
        for (int w = 1; w < 8; w++) {
            float4 p = part4[w][tid];
            a.x += p.x; a.y += p.y; a.z += p.z; a.w += p.w;
        }
        ((float4*)(g_feat + (size_t)l * 3 * D_ + 2 * D_))[tid] = a;
    }
}

// ---------------- final head: logits + log_softmax --------------------------
__global__ void out_kernel(const float* __restrict__ W_out, const float* __restrict__ b_out,
                           float* __restrict__ out)
{
    int l = blockIdx.x;
    int tid = threadIdx.x;        // 224 threads, 7 warps
    int wid = tid >> 5, lane = tid & 31;
    __shared__ float sW[D_ * C_];
    __shared__ float logit[C_];
    __shared__ float s2[2];
    for (int j = tid; j < D_ * C_; j += 224) sW[j] = W_out[j];
    __syncthreads();
    float a = 0.f;
    for (int j = lane; j < D_; j += 32) a += g_h1[l * D_ + j] * sW[j * C_ + wid];
    a = wred(a);
    if (lane == 0) logit[wid] = a + b_out[wid];
    __syncthreads();
    if (tid == 0) {
        float mx = -1e30f;
        for (int c = 0; c < C_; c++) mx = fmaxf(mx, logit[c]);
        float sum = 0.f;
        for (int c = 0; c < C_; c++) sum += expf(logit[c] - mx);
        s2[0] = mx; s2[1] = logf(sum);
    }
    __syncthreads();
    if (tid < C_) out[l * C_ + tid] = logit[tid] - s2[0] - s2[1];
}

// ---------------------------------------------------------------------------
extern "C" void kernel_launch(void* const* d_in, const int* in_sizes, int n_in,
                              void* d_out, int out_size)
{
    const float* utt      = (const float*)d_in[0];
    const int*   str_src  = (const int*)d_in[1];
    const int*   str_dst  = (const int*)d_in[2];
    const int*   str_typ  = (const int*)d_in[3];
    const int*   cpt_src  = (const int*)d_in[4];
    const int*   cpt_dst  = (const int*)d_in[5];
    const float* cpt_w    = (const float*)d_in[6];
    const float* cpt_sen  = (const float*)d_in[7];
    const float* table    = (const float*)d_in[8];
    const float* W_basis  = (const float*)d_in[9];
    const float* comp     = (const float*)d_in[10];
    const float* W_self   = (const float*)d_in[11];
    const float* b_rgcn   = (const float*)d_in[12];
    const float* Wq       = (const float*)d_in[13];
    const float* Wk       = (const float*)d_in[14];
    const float* Wv       = (const float*)d_in[15];
    const float* Wo       = (const float*)d_in[16];
    const float* r_vecs   = (const float*)d_in[17];
    const float* W_fuse   = (const float*)d_in[18];
    const float* b_fuse   = (const float*)d_in[19];
    const float* W_out    = (const float*)d_in[20];
    const float* b_out    = (const float*)d_in[21];
    float* out = (float*)d_out;

    float *Y0, *Y1, *Qb, *Kb, *Vb, *xws, *feat, *h1;
    cudaGetSymbolAddress((void**)&Y0, g_Y0);
    cudaGetSymbolAddress((void**)&Y1, g_Y1);
    cudaGetSymbolAddress((void**)&Qb, g_Q);
    cudaGetSymbolAddress((void**)&Kb, g_Km);
    cudaGetSymbolAddress((void**)&Vb, g_Vm);
    cudaGetSymbolAddress((void**)&xws, g_xws);
    cudaGetSymbolAddress((void**)&feat, g_feat);
    cudaGetSymbolAddress((void**)&h1, g_h1);

    Batch6 p;
    p.B[0] = W_basis;            p.bias[0] = nullptr; p.C[0] = Y0;
    p.B[1] = W_basis + D_ * D_;  p.bias[1] = nullptr; p.C[1] = Y1;
    p.B[2] = Wq;                 p.bias[2] = nullptr; p.C[2] = Qb;
    p.B[3] = Wk;                 p.bias[3] = nullptr; p.C[3] = Kb;
    p.B[4] = Wv;                 p.bias[4] = nullptr; p.C[4] = Vb;
    p.B[5] = W_self;             p.bias[5] = b_rgcn;  p.C[5] = xws;

    dim3 g6((D_ + 31) / 32, (L_ + 31) / 32, 6);
    gemm6_kernel<<<g6, 256>>>(utt, p);

    combo_kernel<<<2 * L_, 640>>>(str_src, str_dst, str_typ, comp, Wo);

    concept_kernel<<<3 * L_ * S_, 256>>>(cpt_src, cpt_dst, cpt_w, cpt_sen, table, r_vecs);
    sym_kernel<<<L_, 256>>>();

    dim3 gg((D_ + 31) / 32, (L_ + 31) / 32);
    gemm_kernel<<<gg, 256>>>(feat, W_fuse, b_fuse, h1, L_, D_, 3 * D_, D_, 1);
    out_kernel<<<L_, 224>>>(W_out, b_out, out);
}

// round 16
// speedup vs baseline: 1.9894x; 1.9894x over previous
#include <cuda_runtime.h>
#include <cuda_bf16.h>
#include <cstdint>
#include <math.h>

#define L_ 256
#define D_ 300
#define S_ 16
#define K_ 16
#define E_ 2048
#define C_ 7
#define NEG_ (-1000000000.0f)
#define D4_ 75
#define GST 3            // cp.async pipeline stages

// ---------------- scratch ---------------------------------------------------
__device__ float g_Y0[L_ * D_];
__device__ float g_Y1[L_ * D_];
__device__ float g_Q[L_ * D_];
__device__ float g_Km[L_ * D_];
__device__ float g_Vm[L_ * D_];
__device__ float g_rel[L_ * D_];
__device__ float g_feat[L_ * 3 * D_];
__device__ float g_nodes[L_ * 3 * S_ * D_];
__device__ float g_scoreb[L_ * 3 * S_];
__device__ int   g_nmask[L_ * 3 * S_];
__device__ float g_h1[L_ * D_];

__device__ __forceinline__ float wred(float v) {
#pragma unroll
    for (int o = 16; o; o >>= 1) v += __shfl_xor_sync(0xFFFFFFFFu, v, o);
    return v;
}
__device__ __forceinline__ float dot4(float4 a, float4 b) {
    return a.x * b.x + a.y * b.y + a.z * b.z + a.w * b.w;
}

// ---------------- cp.async helpers ------------------------------------------
__device__ __forceinline__ void cpa16(unsigned int dst, const float* src, bool p) {
    asm volatile("cp.async.cg.shared.global [%0], [%1], 16, %2;"
                 :: "r"(dst), "l"(src), "r"(p ? 16 : 0));
}
__device__ __forceinline__ void cpcommit() {
    asm volatile("cp.async.commit_group;");
}
template<int N>
__device__ __forceinline__ void cpwait() {
    asm volatile("cp.async.wait_group %0;" :: "n"(N));
}

// ---------------- 3-stage cp.async pipelined 32x32 GEMM ---------------------
__device__ __forceinline__ void gemm_core_async(
    const float* __restrict__ A, const float* __restrict__ B,
    const float* __restrict__ bias, float* __restrict__ C,
    int M, int N, int K, int ldc, int relu,
    float (*As)[32][36], float (*Bs)[32][36])
{
    int t  = threadIdx.x;
    int lr = t >> 3;
    int lc = (t & 7) << 2;
    int tx = t & 31, ty = t >> 5;
    int row0 = blockIdx.y * 32;
    int col0 = blockIdx.x * 32;
    int T = (K + 31) >> 5;

    unsigned int sA = (unsigned int)__cvta_generic_to_shared(&As[0][0][0]);
    unsigned int sB = (unsigned int)__cvta_generic_to_shared(&Bs[0][0][0]);
    const unsigned int stageB = 32 * 36 * 4;
    unsigned int off = (unsigned int)(lr * 36 + lc) * 4;

    float acc[4] = {0.f, 0.f, 0.f, 0.f};

#pragma unroll
    for (int s = 0; s < GST - 1; s++) {
        if (s < T) {
            int k0 = s << 5;
            bool pa = (row0 + lr < M) && (k0 + lc < K);
            const float* pas = pa ? A + (size_t)(row0 + lr) * K + k0 + lc : A;
            cpa16(sA + s * stageB + off, pas, pa);
            bool pb = (k0 + lr < K) && (col0 + lc < N);
            const float* pbs = pb ? B + (size_t)(k0 + lr) * N + col0 + lc : B;
            cpa16(sB + s * stageB + off, pbs, pb);
        }
        cpcommit();
    }

    for (int t0 = 0; t0 < T; t0++) {
        int tl = t0 + GST - 1;
        if (tl < T) {
            int st = tl % GST;
            int k0 = tl << 5;
            bool pa = (row0 + lr < M) && (k0 + lc < K);
            const float* pas = pa ? A + (size_t)(row0 + lr) * K + k0 + lc : A;
            cpa16(sA + st * stageB + off, pas, pa);
            bool pb = (k0 + lr < K) && (col0 + lc < N);
            const float* pbs = pb ? B + (size_t)(k0 + lr) * N + col0 + lc : B;
            cpa16(sB + st * stageB + off, pbs, pb);
        }
        cpcommit();
        cpwait<GST - 2>();
        __syncthreads();
        int st = t0 % GST;
#pragma unroll
        for (int kk = 0; kk < 32; kk++) {
            float bv = Bs[st][kk][tx];
#pragma unroll
            for (int i = 0; i < 4; i++) acc[i] += As[st][ty + 8 * i][kk] * bv;
        }
        __syncthreads();
    }

    int col = col0 + tx;
    if (col < N) {
        float bv = bias ? bias[col] : 0.f;
#pragma unroll
        for (int i = 0; i < 4; i++) {
            int r = row0 + ty + 8 * i;
            if (r < M) {
                float v = acc[i] + bv;
                if (relu) v = fmaxf(v, 0.f);
                C[(size_t)r * ldc + col] = v;
            }
        }
    }
}

struct Batch6 {
    const float* B[6];
    const float* bias[6];
    float* C[6];
    int ldc[6];
};

__global__ void gemm6_kernel(const float* __restrict__ A, Batch6 p)
{
    __shared__ float As[GST][32][36];
    __shared__ float Bs[GST][32][36];
    int z = blockIdx.z;
    gemm_core_async(A, p.B[z], p.bias[z], p.C[z], L_, D_, D_, p.ldc[z], 0, As, Bs);
}

__global__ void gemm_kernel(const float* __restrict__ A, const float* __restrict__ B,
                            const float* __restrict__ bias, float* __restrict__ C,
                            int M, int N, int K, int ldc, int relu)
{
    __shared__ float As[GST][32][36];
    __shared__ float Bs[GST][32][36];
    gemm_core_async(A, B, bias, C, M, N, K, ldc, relu, As, Bs);
}

// ---------------- combo: relatt+Wo GEMV (blocks 0..255) + edge-parallel RGCN
// edge blocks: 64 blocks x 32 edges, 2 edges in flight per iteration.
// g_feat[:,0:300] was pre-initialized by the xws GEMM (with bias).
__global__ void combo_kernel(const int* __restrict__ esrc, const int* __restrict__ edst,
                             const int* __restrict__ etyp, const float* __restrict__ comp,
                             const float* __restrict__ Wo)
{
    int tid = threadIdx.x;          // 640 threads
    if (blockIdx.x < L_) {
        // -------- windowed attention (center query) + rel = attout @ Wo -----
        int l = blockIdx.x;
        int wid = tid >> 5, lane = tid & 31;
        __shared__ float sS[2][3];
        __shared__ float sA[2][3];
        __shared__ float sat[D_];
        int nbr[3];
        nbr[0] = l > 0 ? l - 1 : 0;
        nbr[1] = l;
        nbr[2] = l < L_ - 1 ? l + 1 : L_ - 1;
        if (wid < 6) {
            int h = wid / 3, k = wid % 3;
            const float* q  = g_Q  + l * D_ + h * 150;
            const float* kk = g_Km + nbr[k] * D_ + h * 150;
            float a = 0.f;
            for (int j = lane; j < 150; j += 32) a += q[j] * kk[j];
            a = wred(a);
            if (lane == 0) sS[h][k] = a * rsqrtf(150.f);
        }
        __syncthreads();
        if (tid < 2) {
            float m = fmaxf(sS[tid][0], fmaxf(sS[tid][1], sS[tid][2]));
            float e0 = expf(sS[tid][0] - m), e1 = expf(sS[tid][1] - m), e2 = expf(sS[tid][2] - m);
            float s = e0 + e1 + e2;
            sA[tid][0] = e0 / s; sA[tid][1] = e1 / s; sA[tid][2] = e2 / s;
        }
        __syncthreads();
        for (int j = tid; j < D_; j += 640) {
            int hh = j / 150;
            float acc = 0.f;
#pragma unroll
            for (int kx = 0; kx < 3; kx++) acc += sA[hh][kx] * g_Vm[nbr[kx] * D_ + j];
            sat[j] = acc;
        }
        __syncthreads();
        for (int c = tid; c < D_; c += 640) {
            float a = 0.f;
#pragma unroll 8
            for (int j = 0; j < D_; j++) a += sat[j] * Wo[j * D_ + c];
            g_rel[l * D_ + c] = a;
            g_feat[l * 3 * D_ + D_ + c] = a;
        }
    } else {
        // -------- edge-parallel RGCN scatter --------
        int eb = blockIdx.x - L_;           // 0..63
        int e0 = eb * 32;
        // two edge lanes: group 0 = threads [0,300), group 1 = threads [320,620)
        int grp = tid >= 320;
        int jt  = grp ? tid - 320 : tid;
        if (jt < D_) {
            for (int i = 0; i < 16; i++) {
                int e = e0 + i * 2 + grp;
                int s  = esrc[e];
                int dd = edst[e];
                int ty = etyp[e];
                float c0 = comp[ty * 2], c1 = comp[ty * 2 + 1];
                float msg = c0 * g_Y0[s * D_ + jt] + c1 * g_Y1[s * D_ + jt];
                atomicAdd(&g_feat[dd * 3 * D_ + jt], msg);
            }
        }
    }
}

// ---------------- concept attention: one block per (g,l,s) ------------------
__global__ void concept_kernel(const int* __restrict__ src_ids, const int* __restrict__ dst_ids,
                               const float* __restrict__ wgt, const float* __restrict__ sen,
                               const float* __restrict__ table, const float* __restrict__ rvecs)
{
    int u = blockIdx.x;
    int s = u % S_;
    int l = (u / S_) % L_;
    int g = u / (S_ * L_);
    int tid = threadIdx.x;              // 256 threads, 8 warps
    int lane = tid & 31, wid = tid >> 5;

    __shared__ float4 sd4[K_][D4_];
    __shared__ float4 su4[D4_];
    __shared__ float4 ssrc4[D4_];
    __shared__ float4 rv4s[D4_];
    __shared__ float du[K_], dsr[K_], dn[K_], beta[K_];
    __shared__ int   dmask[K_];
    __shared__ float red[8];
    __shared__ float s_unorm;

    int base = u * K_;
    int r0 = wid * 2, r1 = r0 + 1;
    int pr = (lane < 2) ? dst_ids[base + r0 + lane] : 0;
    int id0 = __shfl_sync(0xFFFFFFFFu, pr, 0);
    int id1 = __shfl_sync(0xFFFFFFFFu, pr, 1);
    if (lane < 2) dmask[r0 + lane] = (pr >= 0);
    int sid = src_ids[u];
    int smask = (sid >= 0);
    if (sid < 0) sid = 0;

    const float4* d0 = (const float4*)(table + (size_t)(id0 >= 0 ? id0 : 0) * D_);
    const float4* d1 = (const float4*)(table + (size_t)(id1 >= 0 ? id1 : 0) * D_);
    bool g3 = (lane + 64) < D4_;
    float4 z4 = make_float4(0.f, 0.f, 0.f, 0.f);
    float4 v0a = d0[lane],      v1a = d1[lane];
    float4 v0b = d0[lane + 32], v1b = d1[lane + 32];
    float4 v0c = g3 ? d0[lane + 64] : z4;
    float4 v1c = g3 ? d1[lane + 64] : z4;

    const float4* rv4p = (const float4*)(rvecs + g * D_);
    if (tid < D4_) {
        float4 sv = ((const float4*)(table + (size_t)sid * D_))[tid];
        ssrc4[tid] = sv;
        rv4s[tid]  = rv4p[tid];
        su4[tid]   = ((const float4*)(g_rel + l * D_))[tid];
    }
    sd4[r0][lane] = v0a;  sd4[r0][lane + 32] = v0b;  if (g3) sd4[r0][lane + 64] = v0c;
    sd4[r1][lane] = v1a;  sd4[r1][lane + 32] = v1b;  if (g3) sd4[r1][lane + 64] = v1c;
    __syncthreads();

    {
        float4 ua = su4[lane], ub = su4[lane + 32], uc = g3 ? su4[lane + 64] : z4;
        float4 sa = ssrc4[lane], sb = ssrc4[lane + 32], sc4 = g3 ? ssrc4[lane + 64] : z4;
        float4 ra = rv4s[lane], rb = rv4s[lane + 32], rc = g3 ? rv4s[lane + 64] : z4;
        float4 pa = make_float4(sa.x * ra.x, sa.y * ra.y, sa.z * ra.z, sa.w * ra.w);
        float4 pb = make_float4(sb.x * rb.x, sb.y * rb.y, sb.z * rb.z, sb.w * rb.w);
        float4 pc = make_float4(sc4.x * rc.x, sc4.y * rc.y, sc4.z * rc.z, sc4.w * rc.w);
        float a0 = dot4(ua, v0a) + dot4(ub, v0b) + dot4(uc, v0c);
        float b0 = dot4(pa, v0a) + dot4(pb, v0b) + dot4(pc, v0c);
        float c0 = dot4(v0a, v0a) + dot4(v0b, v0b) + dot4(v0c, v0c);
        float a1 = dot4(ua, v1a) + dot4(ub, v1b) + dot4(uc, v1c);
        float b1 = dot4(pa, v1a) + dot4(pb, v1b) + dot4(pc, v1c);
        float c1 = dot4(v1a, v1a) + dot4(v1b, v1b) + dot4(v1c, v1c);
        a0 = wred(a0); b0 = wred(b0); c0 = wred(c0);
        a1 = wred(a1); b1 = wred(b1); c1 = wred(c1);
        if (lane == 0) {
            du[r0] = a0; dsr[r0] = b0; dn[r0] = c0;
            du[r1] = a1; dsr[r1] = b1; dn[r1] = c1;
        }
        if (wid == 0) {
            float p = dot4(ua, ua) + dot4(ub, ub) + dot4(uc, uc);
            p = wred(p);
            if (lane == 0) s_unorm = sqrtf(p);
        }
    }
    __syncthreads();

    if (wid == 0) {
        int k = lane & 15;
        int mk = dmask[k];
        float wk = wgt[base + k];
        float se = fabsf(sen[base + k]);
        float unorm = s_unorm;
        float cosv = fabsf(du[k]) / (unorm * sqrtf(dn[k]) + 1e-8f);
        float om = 0.5f * wk * cosv + 0.5f * se;
        float v = mk ? om : NEG_;
        float m = v;
#pragma unroll
        for (int o = 8; o; o >>= 1) m = fmaxf(m, __shfl_xor_sync(0xFFFFFFFFu, m, o));
        float e = expf(v - m);
        float sm = e;
#pragma unroll
        for (int o = 8; o; o >>= 1) sm += __shfl_xor_sync(0xFFFFFFFFu, sm, o);
        float a1v = mk ? e / sm : 0.f;

        float sv = a1v * dsr[k];
        v = mk ? sv : NEG_;
        m = v;
#pragma unroll
        for (int o = 8; o; o >>= 1) m = fmaxf(m, __shfl_xor_sync(0xFFFFFFFFu, m, o));
        e = expf(v - m);
        sm = e;
#pragma unroll
        for (int o = 8; o; o >>= 1) sm += __shfl_xor_sync(0xFFFFFFFFu, sm, o);
        float b2 = a1v * (mk ? e / sm : 0.f);
        if (lane < 16) beta[k] = b2;
    }
    __syncthreads();

    const float* sdf = (const float*)sd4;
    const float* uf  = (const float*)su4;
    const float* sf  = (const float*)ssrc4;
    const float* rvf = (const float*)rv4s;
    int node = l * (3 * S_) + g * S_ + s;
    float part = 0.f;
    for (int j = tid; j < D_; j += 256) {
        float acc = 0.f;
#pragma unroll
        for (int k = 0; k < K_; k++) acc += beta[k] * sdf[k * (D4_ * 4) + j];
        float v = fmaf(rvf[j], acc, sf[j]);
        g_nodes[(size_t)node * D_ + j] = v;
        part += v * uf[j];
    }
    part = wred(part);
    if (lane == 0) red[wid] = part;
    __syncthreads();
    if (tid == 0) {
        float t = 0.f;
        for (int i = 0; i < 8; i++) t += red[i];
        g_scoreb[node] = t;
        g_nmask[node]  = smask;
    }
}

// ---------------- node attention -> sym -> feat[:,600:900] ------------------
__global__ void sym_kernel()
{
    int l = blockIdx.x;
    int tid = threadIdx.x;        // 256
    int lane = tid & 31, wid = tid >> 5;
    __shared__ float att[3 * S_];
    __shared__ float4 part4[8][D4_];
    if (tid < 3 * S_)
        att[tid] = g_nmask[l * 3 * S_ + tid] ? g_scoreb[l * 3 * S_ + tid] : NEG_;
    __syncthreads();
    if (tid == 0) {
        float mx = -1e30f;
        for (int n = 0; n < 3 * S_; n++) mx = fmaxf(mx, att[n]);
        float sum = 0.f;
        for (int n = 0; n < 3 * S_; n++) { float e = expf(att[n] - mx); att[n] = e; sum += e; }
        for (int n = 0; n < 3 * S_; n++)
            att[n] = g_nmask[l * 3 * S_ + n] ? att[n] / sum : 0.f;
    }
    __syncthreads();
    int n0 = wid * 6;
    for (int j = lane; j < D4_; j += 32) {
        float4 a = make_float4(0.f, 0.f, 0.f, 0.f);
#pragma unroll
        for (int q = 0; q < 6; q++) {
            int n = n0 + q;
            float w = att[n];
            float4 v = ((const float4*)(g_nodes + (size_t)(l * 3 * S_ + n) * D_))[j];
            a.x += w * v.x; a.y += w * v.y; a.z += w * v.z; a.w += w * v.w;
        }
        part4[wid][j] = a;
    }
    __syncthreads();
    if (tid < D4_) {
        float4 a = part4[0][tid];
#pragma unroll
        for (int w = 1; w < 8; w++) {
            float4 p = part4[w][tid];
            a.x += p.x; a.y += p.y; a.z += p.z; a.w += p.w;
        }
        ((float4*)(g_feat + (size_t)l * 3 * D_ + 2 * D_))[tid] = a;
    }
}

// ---------------- final head: logits + log_softmax --------------------------
__global__ void out_kernel(const float* __restrict__ W_out, const float* __restrict__ b_out,
                           float* __restrict__ out)
{
    int l = blockIdx.x;
    int tid = threadIdx.x;        // 224 threads, 7 warps
    int wid = tid >> 5, lane = tid & 31;
    __shared__ float sW[D_ * C_];
    __shared__ float logit[C_];
    __shared__ float s2[2];
    for (int j = tid; j < D_ * C_; j += 224) sW[j] = W_out[j];
    __syncthreads();
    float a = 0.f;
    for (int j = lane; j < D_; j += 32) a += g_h1[l * D_ + j] * sW[j * C_ + wid];
    a = wred(a);
    if (lane == 0) logit[wid] = a + b_out[wid];
    __syncthreads();
    if (tid == 0) {
        float mx = -1e30f;
        for (int c = 0; c < C_; c++) mx = fmaxf(mx, logit[c]);
        float sum = 0.f;
        for (int c = 0; c < C_; c++) sum += expf(logit[c] - mx);
        s2[0] = mx; s2[1] = logf(sum);
    }
    __syncthreads();
    if (tid < C_) out[l * C_ + tid] = logit[tid] - s2[0] - s2[1];
}

// ---------------------------------------------------------------------------
extern "C" void kernel_launch(void* const* d_in, const int* in_sizes, int n_in,
                              void* d_out, int out_size)
{
    const float* utt      = (const float*)d_in[0];
    const int*   str_src  = (const int*)d_in[1];
    const int*   str_dst  = (const int*)d_in[2];
    const int*   str_typ  = (const int*)d_in[3];
    const int*   cpt_src  = (const int*)d_in[4];
    const int*   cpt_dst  = (const int*)d_in[5];
    const float* cpt_w    = (const float*)d_in[6];
    const float* cpt_sen  = (const float*)d_in[7];
    const float* table    = (const float*)d_in[8];
    const float* W_basis  = (const float*)d_in[9];
    const float* comp     = (const float*)d_in[10];
    const float* W_self   = (const float*)d_in[11];
    const float* b_rgcn   = (const float*)d_in[12];
    const float* Wq       = (const float*)d_in[13];
    const float* Wk       = (const float*)d_in[14];
    const float* Wv       = (const float*)d_in[15];
    const float* Wo       = (const float*)d_in[16];
    const float* r_vecs   = (const float*)d_in[17];
    const float* W_fuse   = (const float*)d_in[18];
    const float* b_fuse   = (const float*)d_in[19];
    const float* W_out    = (const float*)d_in[20];
    const float* b_out    = (const float*)d_in[21];
    float* out = (float*)d_out;

    float *Y0, *Y1, *Qb, *Kb, *Vb, *feat, *h1;
    cudaGetSymbolAddress((void**)&Y0, g_Y0);
    cudaGetSymbolAddress((void**)&Y1, g_Y1);
    cudaGetSymbolAddress((void**)&Qb, g_Q);
    cudaGetSymbolAddress((void**)&Kb, g_Km);
    cudaGetSymbolAddress((void**)&Vb, g_Vm);
    cudaGetSymbolAddress((void**)&feat, g_feat);
    cudaGetSymbolAddress((void**)&h1, g_h1);

    Batch6 p;
    p.B[0] = W_basis;            p.bias[0] = nullptr; p.C[0] = Y0;   p.ldc[0] = D_;
    p.B[1] = W_basis + D_ * D_;  p.bias[1] = nullptr; p.C[1] = Y1;   p.ldc[1] = D_;
    p.B[2] = Wq;                 p.bias[2] = nullptr; p.C[2] = Qb;   p.ldc[2] = D_;
    p.B[3] = Wk;                 p.bias[3] = nullptr; p.C[3] = Kb;   p.ldc[3] = D_;
    p.B[4] = Wv;                 p.bias[4] = nullptr; p.C[4] = Vb;   p.ldc[4] = D_;
    p.B[5] = W_self;             p.bias[5] = b_rgcn;  p.C[5] = feat; p.ldc[5] = 3 * D_;

    dim3 g6((D_ + 31) / 32, (L_ + 31) / 32, 6);
    gemm6_kernel<<<g6, 256>>>(utt, p);

    // 256 relatt blocks + 64 edge-parallel RGCN blocks
    combo_kernel<<<L_ + 64, 640>>>(str_src, str_dst, str_typ, comp, Wo);

    concept_kernel<<<3 * L_ * S_, 256>>>(cpt_src, cpt_dst, cpt_w, cpt_sen, table, r_vecs);
    sym_kernel<<<L_, 256>>>();

    dim3 gg((D_ + 31) / 32, (L_ + 31) / 32);
    gemm_kernel<<<gg, 256>>>(feat, W_fuse, b_fuse, h1, L_, D_, 3 * D_, D_, 1);
    out_kernel<<<L_, 224>>>(W_out, b_out, out);
}

// round 17
// speedup vs baseline: 2.0111x; 1.0109x over previous
#include <cuda_runtime.h>
#include <cuda_bf16.h>
#include <cstdint>
#include <math.h>

#define L_ 256
#define D_ 300
#define S_ 16
#define K_ 16
#define E_ 2048
#define C_ 7
#define NEG_ (-1000000000.0f)
#define D4_ 75
#define GST 3            // cp.async pipeline stages

// ---------------- scratch ---------------------------------------------------
__device__ float g_Y0[L_ * D_];
__device__ float g_Y1[L_ * D_];
__device__ float g_Q[L_ * D_];
__device__ float g_Km[L_ * D_];
__device__ float g_Vm[L_ * D_];
__device__ float g_rel[L_ * D_];
__device__ float g_feat[L_ * 3 * D_];
__device__ float g_nodes[L_ * 3 * S_ * D_];
__device__ float g_scoreb[L_ * 3 * S_];
__device__ int   g_nmask[L_ * 3 * S_];
__device__ float g_h1[L_ * D_];

__device__ __forceinline__ float wred(float v) {
#pragma unroll
    for (int o = 16; o; o >>= 1) v += __shfl_xor_sync(0xFFFFFFFFu, v, o);
    return v;
}
__device__ __forceinline__ float dot4(float4 a, float4 b) {
    return a.x * b.x + a.y * b.y + a.z * b.z + a.w * b.w;
}

// ---------------- cp.async helpers ------------------------------------------
__device__ __forceinline__ void cpa16(unsigned int dst, const float* src, bool p) {
    asm volatile("cp.async.cg.shared.global [%0], [%1], 16, %2;"
                 :: "r"(dst), "l"(src), "r"(p ? 16 : 0));
}
__device__ __forceinline__ void cpcommit() {
    asm volatile("cp.async.commit_group;");
}
template<int N>
__device__ __forceinline__ void cpwait() {
    asm volatile("cp.async.wait_group %0;" :: "n"(N));
}

// ---------------- 3-stage cp.async pipelined 32x32 GEMM ---------------------
__device__ __forceinline__ void gemm_core_async(
    const float* __restrict__ A, const float* __restrict__ B,
    const float* __restrict__ bias, float* __restrict__ C,
    int M, int N, int K, int ldc, int relu,
    float (*As)[32][36], float (*Bs)[32][36])
{
    int t  = threadIdx.x;
    int lr = t >> 3;
    int lc = (t & 7) << 2;
    int tx = t & 31, ty = t >> 5;
    int row0 = blockIdx.y * 32;
    int col0 = blockIdx.x * 32;
    int T = (K + 31) >> 5;

    unsigned int sA = (unsigned int)__cvta_generic_to_shared(&As[0][0][0]);
    unsigned int sB = (unsigned int)__cvta_generic_to_shared(&Bs[0][0][0]);
    const unsigned int stageB = 32 * 36 * 4;
    unsigned int off = (unsigned int)(lr * 36 + lc) * 4;

    float acc[4] = {0.f, 0.f, 0.f, 0.f};

#pragma unroll
    for (int s = 0; s < GST - 1; s++) {
        if (s < T) {
            int k0 = s << 5;
            bool pa = (row0 + lr < M) && (k0 + lc < K);
            const float* pas = pa ? A + (size_t)(row0 + lr) * K + k0 + lc : A;
            cpa16(sA + s * stageB + off, pas, pa);
            bool pb = (k0 + lr < K) && (col0 + lc < N);
            const float* pbs = pb ? B + (size_t)(k0 + lr) * N + col0 + lc : B;
            cpa16(sB + s * stageB + off, pbs, pb);
        }
        cpcommit();
    }

    for (int t0 = 0; t0 < T; t0++) {
        int tl = t0 + GST - 1;
        if (tl < T) {
            int st = tl % GST;
            int k0 = tl << 5;
            bool pa = (row0 + lr < M) && (k0 + lc < K);
            const float* pas = pa ? A + (size_t)(row0 + lr) * K + k0 + lc : A;
            cpa16(sA + st * stageB + off, pas, pa);
            bool pb = (k0 + lr < K) && (col0 + lc < N);
            const float* pbs = pb ? B + (size_t)(k0 + lr) * N + col0 + lc : B;
            cpa16(sB + st * stageB + off, pbs, pb);
        }
        cpcommit();
        cpwait<GST - 2>();
        __syncthreads();
        int st = t0 % GST;
#pragma unroll
        for (int kk = 0; kk < 32; kk++) {
            float bv = Bs[st][kk][tx];
#pragma unroll
            for (int i = 0; i < 4; i++) acc[i] += As[st][ty + 8 * i][kk] * bv;
        }
        __syncthreads();
    }

    int col = col0 + tx;
    if (col < N) {
        float bv = bias ? bias[col] : 0.f;
#pragma unroll
        for (int i = 0; i < 4; i++) {
            int r = row0 + ty + 8 * i;
            if (r < M) {
                float v = acc[i] + bv;
                if (relu) v = fmaxf(v, 0.f);
                C[(size_t)r * ldc + col] = v;
            }
        }
    }
}

struct Batch6 {
    const float* B[6];
    const float* bias[6];
    float* C[6];
    int ldc[6];
};

__global__ void gemm6_kernel(const float* __restrict__ A, Batch6 p)
{
    __shared__ float As[GST][32][36];
    __shared__ float Bs[GST][32][36];
    int z = blockIdx.z;
    gemm_core_async(A, p.B[z], p.bias[z], p.C[z], L_, D_, D_, p.ldc[z], 0, As, Bs);
}

__global__ void gemm_kernel(const float* __restrict__ A, const float* __restrict__ B,
                            const float* __restrict__ bias, float* __restrict__ C,
                            int M, int N, int K, int ldc, int relu)
{
    __shared__ float As[GST][32][36];
    __shared__ float Bs[GST][32][36];
    gemm_core_async(A, B, bias, C, M, N, K, ldc, relu, As, Bs);
}

// ---------------- combo: relatt+Wo GEMV (blocks 0..255) + edge-parallel RGCN
__global__ void combo_kernel(const int* __restrict__ esrc, const int* __restrict__ edst,
                             const int* __restrict__ etyp, const float* __restrict__ comp,
                             const float* __restrict__ Wo)
{
    int tid = threadIdx.x;          // 640 threads
    if (blockIdx.x < L_) {
        int l = blockIdx.x;
        int wid = tid >> 5, lane = tid & 31;
        __shared__ float sS[2][3];
        __shared__ float sA[2][3];
        __shared__ float sat[D_];
        int nbr[3];
        nbr[0] = l > 0 ? l - 1 : 0;
        nbr[1] = l;
        nbr[2] = l < L_ - 1 ? l + 1 : L_ - 1;
        if (wid < 6) {
            int h = wid / 3, k = wid % 3;
            const float* q  = g_Q  + l * D_ + h * 150;
            const float* kk = g_Km + nbr[k] * D_ + h * 150;
            float a = 0.f;
            for (int j = lane; j < 150; j += 32) a += q[j] * kk[j];
            a = wred(a);
            if (lane == 0) sS[h][k] = a * rsqrtf(150.f);
        }
        __syncthreads();
        if (tid < 2) {
            float m = fmaxf(sS[tid][0], fmaxf(sS[tid][1], sS[tid][2]));
            float e0 = expf(sS[tid][0] - m), e1 = expf(sS[tid][1] - m), e2 = expf(sS[tid][2] - m);
            float s = e0 + e1 + e2;
            sA[tid][0] = e0 / s; sA[tid][1] = e1 / s; sA[tid][2] = e2 / s;
        }
        __syncthreads();
        for (int j = tid; j < D_; j += 640) {
            int hh = j / 150;
            float acc = 0.f;
#pragma unroll
            for (int kx = 0; kx < 3; kx++) acc += sA[hh][kx] * g_Vm[nbr[kx] * D_ + j];
            sat[j] = acc;
        }
        __syncthreads();
        for (int c = tid; c < D_; c += 640) {
            float a = 0.f;
#pragma unroll 8
            for (int j = 0; j < D_; j++) a += sat[j] * Wo[j * D_ + c];
            g_rel[l * D_ + c] = a;
            g_feat[l * 3 * D_ + D_ + c] = a;
        }
    } else {
        // -------- edge-parallel RGCN scatter --------
        int eb = blockIdx.x - L_;           // 0..63
        int e0 = eb * 32;
        int grp = tid >= 320;
        int jt  = grp ? tid - 320 : tid;
        if (jt < D_) {
            for (int i = 0; i < 16; i++) {
                int e = e0 + i * 2 + grp;
                int s  = esrc[e];
                int dd = edst[e];
                int ty = etyp[e];
                float c0 = comp[ty * 2], c1 = comp[ty * 2 + 1];
                float msg = c0 * g_Y0[s * D_ + jt] + c1 * g_Y1[s * D_ + jt];
                atomicAdd(&g_feat[dd * 3 * D_ + jt], msg);
            }
        }
    }
}

// ---------------- concept attention: one block per (g,l,s) ------------------
__global__ void concept_kernel(const int* __restrict__ src_ids, const int* __restrict__ dst_ids,
                               const float* __restrict__ wgt, const float* __restrict__ sen,
                               const float* __restrict__ table, const float* __restrict__ rvecs)
{
    int u = blockIdx.x;
    int s = u % S_;
    int l = (u / S_) % L_;
    int g = u / (S_ * L_);
    int tid = threadIdx.x;              // 256 threads, 8 warps
    int lane = tid & 31, wid = tid >> 5;

    __shared__ float4 sd4[K_][D4_];
    __shared__ float4 su4[D4_];
    __shared__ float4 ssrc4[D4_];
    __shared__ float4 rv4s[D4_];
    __shared__ float du[K_], dsr[K_], dn[K_], beta[K_];
    __shared__ float swk[K_], sse[K_];
    __shared__ int   dmask[K_];
    __shared__ float red[8];
    __shared__ float s_unorm;

    int base = u * K_;
    int r0 = wid * 2, r1 = r0 + 1;
    int pr = (lane < 2) ? dst_ids[base + r0 + lane] : 0;
    int id0 = __shfl_sync(0xFFFFFFFFu, pr, 0);
    int id1 = __shfl_sync(0xFFFFFFFFu, pr, 1);
    if (lane < 2) dmask[r0 + lane] = (pr >= 0);
    // hoist metadata loads: issued alongside the row gathers
    if (wid == 0 && lane < K_) {
        swk[lane] = wgt[base + lane];
        sse[lane] = fabsf(sen[base + lane]);
    }
    int sid = src_ids[u];
    int smask = (sid >= 0);
    if (sid < 0) sid = 0;

    const float4* d0 = (const float4*)(table + (size_t)(id0 >= 0 ? id0 : 0) * D_);
    const float4* d1 = (const float4*)(table + (size_t)(id1 >= 0 ? id1 : 0) * D_);
    bool g3 = (lane + 64) < D4_;
    float4 z4 = make_float4(0.f, 0.f, 0.f, 0.f);
    float4 v0a = d0[lane],      v1a = d1[lane];
    float4 v0b = d0[lane + 32], v1b = d1[lane + 32];
    float4 v0c = g3 ? d0[lane + 64] : z4;
    float4 v1c = g3 ? d1[lane + 64] : z4;

    const float4* rv4p = (const float4*)(rvecs + g * D_);
    if (tid < D4_) {
        float4 sv = ((const float4*)(table + (size_t)sid * D_))[tid];
        ssrc4[tid] = sv;
        rv4s[tid]  = rv4p[tid];
        su4[tid]   = ((const float4*)(g_rel + l * D_))[tid];
    }
    sd4[r0][lane] = v0a;  sd4[r0][lane + 32] = v0b;  if (g3) sd4[r0][lane + 64] = v0c;
    sd4[r1][lane] = v1a;  sd4[r1][lane + 32] = v1b;  if (g3) sd4[r1][lane + 64] = v1c;
    __syncthreads();

    {
        float4 ua = su4[lane], ub = su4[lane + 32], uc = g3 ? su4[lane + 64] : z4;
        float4 sa = ssrc4[lane], sb = ssrc4[lane + 32], sc4 = g3 ? ssrc4[lane + 64] : z4;
        float4 ra = rv4s[lane], rb = rv4s[lane + 32], rc = g3 ? rv4s[lane + 64] : z4;
        float4 pa = make_float4(sa.x * ra.x, sa.y * ra.y, sa.z * ra.z, sa.w * ra.w);
        float4 pb = make_float4(sb.x * rb.x, sb.y * rb.y, sb.z * rb.z, sb.w * rb.w);
        float4 pc = make_float4(sc4.x * rc.x, sc4.y * rc.y, sc4.z * rc.z, sc4.w * rc.w);
        float a0 = dot4(ua, v0a) + dot4(ub, v0b) + dot4(uc, v0c);
        float b0 = dot4(pa, v0a) + dot4(pb, v0b) + dot4(pc, v0c);
        float c0 = dot4(v0a, v0a) + dot4(v0b, v0b) + dot4(v0c, v0c);
        float a1 = dot4(ua, v1a) + dot4(ub, v1b) + dot4(uc, v1c);
        float b1 = dot4(pa, v1a) + dot4(pb, v1b) + dot4(pc, v1c);
        float c1 = dot4(v1a, v1a) + dot4(v1b, v1b) + dot4(v1c, v1c);
        a0 = wred(a0); b0 = wred(b0); c0 = wred(c0);
        a1 = wred(a1); b1 = wred(b1); c1 = wred(c1);
        if (lane == 0) {
            du[r0] = a0; dsr[r0] = b0; dn[r0] = c0;
            du[r1] = a1; dsr[r1] = b1; dn[r1] = c1;
        }
        if (wid == 0) {
            float p = dot4(ua, ua) + dot4(ub, ub) + dot4(uc, uc);
            p = wred(p);
            if (lane == 0) s_unorm = sqrtf(p);
        }
    }
    __syncthreads();

    if (wid == 0) {
        int k = lane & 15;
        int mk = dmask[k];
        float wk = swk[k];
        float se = sse[k];
        float unorm = s_unorm;
        float cosv = fabsf(du[k]) / (unorm * sqrtf(dn[k]) + 1e-8f);
        float om = 0.5f * wk * cosv + 0.5f * se;
        float v = mk ? om : NEG_;
        float m = v;
#pragma unroll
        for (int o = 8; o; o >>= 1) m = fmaxf(m, __shfl_xor_sync(0xFFFFFFFFu, m, o));
        float e = expf(v - m);
        float sm = e;
#pragma unroll
        for (int o = 8; o; o >>= 1) sm += __shfl_xor_sync(0xFFFFFFFFu, sm, o);
        float a1v = mk ? e / sm : 0.f;

        float sv = a1v * dsr[k];
        v = mk ? sv : NEG_;
        m = v;
#pragma unroll
        for (int o = 8; o; o >>= 1) m = fmaxf(m, __shfl_xor_sync(0xFFFFFFFFu, m, o));
        e = expf(v - m);
        sm = e;
#pragma unroll
        for (int o = 8; o; o >>= 1) sm += __shfl_xor_sync(0xFFFFFFFFu, sm, o);
        float b2 = a1v * (mk ? e / sm : 0.f);
        if (lane < 16) beta[k] = b2;
    }
    __syncthreads();

    const float* sdf = (const float*)sd4;
    const float* uf  = (const float*)su4;
    const float* sf  = (const float*)ssrc4;
    const float* rvf = (const float*)rv4s;
    int node = l * (3 * S_) + g * S_ + s;
    float part = 0.f;
    for (int j = tid; j < D_; j += 256) {
        float acc = 0.f;
#pragma unroll
        for (int k = 0; k < K_; k++) acc += beta[k] * sdf[k * (D4_ * 4) + j];
        float v = fmaf(rvf[j], acc, sf[j]);
        g_nodes[(size_t)node * D_ + j] = v;
        part += v * uf[j];
    }
    part = wred(part);
    if (lane == 0) red[wid] = part;
    __syncthreads();
    if (tid == 0) {
        float t = 0.f;
        for (int i = 0; i < 8; i++) t += red[i];
        g_scoreb[node] = t;
        g_nmask[node]  = smask;
    }
}

// ---------------- node attention -> sym -> feat[:,600:900] ------------------
// grid 2*L: block (l, half). Each block handles half of the 75 float4 columns.
__global__ void sym_kernel()
{
    int l = blockIdx.x >> 1;
    int half = blockIdx.x & 1;
    int tid = threadIdx.x;        // 256
    int lane = tid & 31, wid = tid >> 5;
    int j0 = half ? 38 : 0;
    int j1 = half ? D4_ : 38;
    __shared__ float att[3 * S_];
    __shared__ float4 part4[8][38];
    if (tid < 3 * S_)
        att[tid] = g_nmask[l * 3 * S_ + tid] ? g_scoreb[l * 3 * S_ + tid] : NEG_;
    __syncthreads();
    if (tid == 0) {
        float mx = -1e30f;
        for (int n = 0; n < 3 * S_; n++) mx = fmaxf(mx, att[n]);
        float sum = 0.f;
        for (int n = 0; n < 3 * S_; n++) { float e = expf(att[n] - mx); att[n] = e; sum += e; }
        for (int n = 0; n < 3 * S_; n++)
            att[n] = g_nmask[l * 3 * S_ + n] ? att[n] / sum : 0.f;
    }
    __syncthreads();
    int n0 = wid * 6;
    for (int j = j0 + lane; j < j1; j += 32) {
        float4 a = make_float4(0.f, 0.f, 0.f, 0.f);
#pragma unroll
        for (int q = 0; q < 6; q++) {
            int n = n0 + q;
            float w = att[n];
            float4 v = ((const float4*)(g_nodes + (size_t)(l * 3 * S_ + n) * D_))[j];
            a.x += w * v.x; a.y += w * v.y; a.z += w * v.z; a.w += w * v.w;
        }
        part4[wid][j - j0] = a;
    }
    __syncthreads();
    if (tid < j1 - j0) {
        float4 a = part4[0][tid];
#pragma unroll
        for (int w = 1; w < 8; w++) {
            float4 p = part4[w][tid];
            a.x += p.x; a.y += p.y; a.z += p.z; a.w += p.w;
        }
        ((float4*)(g_feat + (size_t)l * 3 * D_ + 2 * D_))[j0 + tid] = a;
    }
}

// ---------------- final head: logits + log_softmax --------------------------
__global__ void out_kernel(const float* __restrict__ W_out, const float* __restrict__ b_out,
                           float* __restrict__ out)
{
    int l = blockIdx.x;
    int tid = threadIdx.x;        // 224 threads, 7 warps
    int wid = tid >> 5, lane = tid & 31;
    __shared__ float sW[D_ * C_];
    __shared__ float logit[C_];
    __shared__ float s2[2];
    for (int j = tid; j < D_ * C_; j += 224) sW[j] = W_out[j];
    __syncthreads();
    float a = 0.f;
    for (int j = lane; j < D_; j += 32) a += g_h1[l * D_ + j] * sW[j * C_ + wid];
    a = wred(a);
    if (lane == 0) logit[wid] = a + b_out[wid];
    __syncthreads();
    if (tid == 0) {
        float mx = -1e30f;
        for (int c = 0; c < C_; c++) mx = fmaxf(mx, logit[c]);
        float sum = 0.f;
        for (int c = 0; c < C_; c++) sum += expf(logit[c] - mx);
        s2[0] = mx; s2[1] = logf(sum);
    }
    __syncthreads();
    if (tid < C_) out[l * C_ + tid] = logit[tid] - s2[0] - s2[1];
}

// ---------------------------------------------------------------------------
extern "C" void kernel_launch(void* const* d_in, const int* in_sizes, int n_in,
                              void* d_out, int out_size)
{
    const float* utt      = (const float*)d_in[0];
    const int*   str_src  = (const int*)d_in[1];
    const int*   str_dst  = (const int*)d_in[2];
    const int*   str_typ  = (const int*)d_in[3];
    const int*   cpt_src  = (const int*)d_in[4];
    const int*   cpt_dst  = (const int*)d_in[5];
    const float* cpt_w    = (const float*)d_in[6];
    const float* cpt_sen  = (const float*)d_in[7];
    const float* table    = (const float*)d_in[8];
    const float* W_basis  = (const float*)d_in[9];
    const float* comp     = (const float*)d_in[10];
    const float* W_self   = (const float*)d_in[11];
    const float* b_rgcn   = (const float*)d_in[12];
    const float* Wq       = (const float*)d_in[13];
    const float* Wk       = (const float*)d_in[14];
    const float* Wv       = (const float*)d_in[15];
    const float* Wo       = (const float*)d_in[16];
    const float* r_vecs   = (const float*)d_in[17];
    const float* W_fuse   = (const float*)d_in[18];
    const float* b_fuse   = (const float*)d_in[19];
    const float* W_out    = (const float*)d_in[20];
    const float* b_out    = (const float*)d_in[21];
    float* out = (float*)d_out;

    float *Y0, *Y1, *Qb, *Kb, *Vb, *feat, *h1;
    cudaGetSymbolAddress((void**)&Y0, g_Y0);
    cudaGetSymbolAddress((void**)&Y1, g_Y1);
    cudaGetSymbolAddress((void**)&Qb, g_Q);
    cudaGetSymbolAddress((void**)&Kb, g_Km);
    cudaGetSymbolAddress((void**)&Vb, g_Vm);
    cudaGetSymbolAddress((void**)&feat, g_feat);
    cudaGetSymbolAddress((void**)&h1, g_h1);

    Batch6 p;
    p.B[0] = W_basis;            p.bias[0] = nullptr; p.C[0] = Y0;   p.ldc[0] = D_;
    p.B[1] = W_basis + D_ * D_;  p.bias[1] = nullptr; p.C[1] = Y1;   p.ldc[1] = D_;
    p.B[2] = Wq;                 p.bias[2] = nullptr; p.C[2] = Qb;   p.ldc[2] = D_;
    p.B[3] = Wk;                 p.bias[3] = nullptr; p.C[3] = Kb;   p.ldc[3] = D_;
    p.B[4] = Wv;                 p.bias[4] = nullptr; p.C[4] = Vb;   p.ldc[4] = D_;
    p.B[5] = W_self;             p.bias[5] = b_rgcn;  p.C[5] = feat; p.ldc[5] = 3 * D_;

    dim3 g6((D_ + 31) / 32, (L_ + 31) / 32, 6);
    gemm6_kernel<<<g6, 256>>>(utt, p);

    combo_kernel<<<L_ + 64, 640>>>(str_src, str_dst, str_typ, comp, Wo);

    concept_kernel<<<3 * L_ * S_, 256>>>(cpt_src, cpt_dst, cpt_w, cpt_sen, table, r_vecs);
    sym_kernel<<<2 * L_, 256>>>();

    dim3 gg((D_ + 31) / 32, (L_ + 31) / 32);
    gemm_kernel<<<gg, 256>>>(feat, W_fuse, b_fuse, h1, L_, D_, 3 * D_, D_, 1);
    out_kernel<<<L_, 224>>>(W_out, b_out, out);
}